// round 7
// baseline (speedup 1.0000x reference)
#include <cuda_runtime.h>
#include <math.h>

#define NB 16
#define NT 60
#define NCLS 80

__constant__ float cANW[9] = {12.f,19.f,40.f,36.f,76.f,72.f,142.f,192.f,459.f};
__constant__ float cANH[9] = {16.f,36.f,28.f,75.f,55.f,146.f,110.f,243.f,401.f};
// atan(w/h) per anchor — scale-invariant constants (<5e-6 abs err; argmax gaps O(1e-2))
__constant__ float cATAN[9] = {0.6435011f, 0.4856221f, 0.9600704f,
                               0.4475200f, 0.9443511f, 0.4581533f,
                               0.9117062f, 0.6686896f, 0.8527381f};

#define FSQ0 5776
#define FSQ1 1444
#define FSQ2 361
#define NC0 (3*FSQ0)
#define NC1 (3*FSQ1)
#define NC2 (3*FSQ2)
#define CMOFF1 (NB*NC0)
#define CMOFF2 (CMOFF1+NB*NC1)
#define NCM    (CMOFF2+NB*NC2)

#define TPB 256
#define CELLS 1024
#define CH0 17
#define CH1 5
#define CH2 2
#define MB 60
#define MAINB (NB*(CH0+CH1+CH2))   /* 384 */
#define GRID (1+MB+MAINB)          /* 445: block0=prep, 1..60=match, rest=main */

__device__ float4 g_tbox[3][NB][NT];      // corner form: (tlx, tly, brx, bry)
__device__ float  g_tarea3[3][NB][NT];    // tw*th/3
__device__ int    g_minfo[3][NB][NT];
__device__ int    g_validf[NB*NT];
__device__ float4 g_cbox[3][NB][NT];      // compacted, corner form
__device__ float  g_car3[3][NB][NT];
__device__ int    g_cnv[3][NB];
__device__ int    g_hm[3][NB];
__device__ __align__(16) int g_cm[NCM];   // monotone via atomicMax; replay-idempotent
__device__ int    g_nmatch;
__device__ int2   g_mlist[NB*NT];
__device__ int    g_done;
__device__ int    g_flag;                 // prep-done flag; reset by final block each run

__device__ __forceinline__ float clogf_(float v){ return fmaxf(__logf(v), -100.0f); }
__device__ __forceinline__ float sigf_(float v){ return __fdividef(1.0f, 1.0f + __expf(-v)); }

__device__ __forceinline__ void waitflag(){
  if (threadIdx.x == 0){
    volatile int* vf = &g_flag;
    while (*vf == 0) __nanosleep(128);
    __threadfence();
  }
  __syncthreads();
}

// ------------------------------------------------------------------ per-thread main context (prep-independent part)
template<int L, int FS>
struct Ctx {
  float so[4], plx[4], ply[4], phx[4], phy[4], ap3[4];
  int base;
};

template<int L, int FS>
__device__ __forceinline__ void main_pre(const float* __restrict__ x, int b, int chunk, Ctx<L,FS>& c){
  constexpr int FSQ = FS*FS;
  constexpr float invs = (L==0) ? 0.125f : 0.0625f;
  c.base = chunk*CELLS + (int)threadIdx.x*4;
  #pragma unroll
  for (int k = 0; k < 4; k++){
    c.so[k] = 0.f; c.plx[k] = 3e4f; c.phx[k] = 3e4f; c.ply[k] = 0.f; c.phy[k] = 0.f; c.ap3[k] = 1.f;
  }
  if (c.base < 3*FSQ){
    int a = c.base/FSQ, cell = c.base - a*FSQ;
    int j0 = cell / FS, i0 = cell - j0*FS;            // FS%4==0 => 4 cells share a row
    const float* xp = x + (b*255 + a*85)*FSQ + cell;
    float4 O0 = __ldg((const float4*)(xp));
    float4 O1 = __ldg((const float4*)(xp+FSQ));
    float4 O2 = __ldg((const float4*)(xp+2*FSQ));
    float4 O3 = __ldg((const float4*)(xp+3*FSQ));
    float4 O4 = __ldg((const float4*)(xp+4*FSQ));
    float AW = cANW[3*L+a]*invs, AH = cANH[3*L+a]*invs;
    float o0a[4] = {O0.x,O0.y,O0.z,O0.w};
    float o1a[4] = {O1.x,O1.y,O1.z,O1.w};
    float o2a[4] = {O2.x,O2.y,O2.z,O2.w};
    float o3a[4] = {O3.x,O3.y,O3.z,O3.w};
    float o4a[4] = {O4.x,O4.y,O4.z,O4.w};
    float fj = (float)j0;
    #pragma unroll
    for (int k = 0; k < 4; k++){
      c.so[k] = sigf_(o4a[k]);
      float pw = __expf(o2a[k])*AW, ph = __expf(o3a[k])*AH;
      float px = (float)(i0+k) + sigf_(o0a[k]);
      float py = fj + sigf_(o1a[k]);
      float hw = 0.5f*pw, hh = 0.5f*ph;
      c.plx[k] = px-hw; c.phx[k] = px+hw; c.ply[k] = py-hh; c.phy[k] = py+hh;
      c.ap3[k] = pw*ph*(1.0f/3.0f);
    }
  }
}

template<int L, int FS, int CMOFF>
__device__ __forceinline__ void main_post(int b, const Ctx<L,FS>& c, int nv, int hm,
    const float4* s_box, const float* s_ar3, float* acc){
  constexpr int FSQ = FS*FS;
  bool un[4] = {false,false,false,false};
  if (c.base < 3*FSQ){
    int4 CM = *(const int4*)&g_cm[CMOFF + b*3*FSQ + c.base];
    int cma[4] = {CM.x,CM.y,CM.z,CM.w};
    #pragma unroll
    for (int k = 0; k < 4; k++){
      if (cma[k]){ acc[2] += -clogf_(c.so[k]); float e = c.so[k]-1.f; acc[4] += e*e; }
      else un[k] = true;
    }
  }
  float vmax[4] = {-1e30f,-1e30f,-1e30f,-1e30f};
  if (hm){
    #pragma unroll 2
    for (int t = 0; t < nv; t++){
      float4 tb = s_box[t];
      float ar3 = s_ar3[t];
      #pragma unroll
      for (int k = 0; k < 4; k++){
        float wi = fmaxf(fminf(c.phx[k], tb.z) - fmaxf(c.plx[k], tb.x), 0.f);
        float hi = fminf(c.phy[k], tb.w) - fmaxf(c.ply[k], tb.y);
        vmax[k] = fmaxf(vmax[k], fmaf(wi, hi, -ar3));   // iou>.5 <=> ai-at/3 > ap/3
      }
    }
  }
  #pragma unroll
  for (int k = 0; k < 4; k++){
    if (un[k] && !(vmax[k] > c.ap3[k])){ acc[2] += -clogf_(1.f - c.so[k]); acc[4] += c.so[k]*c.so[k]; }
  }
}

// scalar variant for L2 (FSQ=361, not divisible by 4)
struct Ctx2 {
  float so[4], plx[4], ply[4], phx[4], phy[4], ap3[4];
  int base;
};

__device__ __forceinline__ void main_pre2(const float* __restrict__ x, int b, int chunk, Ctx2& c){
  constexpr int FSQ = FSQ2;
  constexpr float invs = 0.03125f;
  c.base = chunk*CELLS + (int)threadIdx.x;
  #pragma unroll
  for (int k = 0; k < 4; k++){
    int cc = c.base + k*TPB;
    c.so[k] = 0.f; c.plx[k] = 3e4f; c.phx[k] = 3e4f; c.ply[k] = 0.f; c.phy[k] = 0.f; c.ap3[k] = 1.f;
    if (cc < 3*FSQ){
      int a = cc/FSQ, cell = cc - a*FSQ;
      const float* xp = x + (b*255 + a*85)*FSQ + cell;
      c.so[k] = sigf_(__ldg(xp + 4*FSQ));
      float AW = cANW[6+a]*invs, AH = cANH[6+a]*invs;
      float pw = __expf(__ldg(xp+2*FSQ))*AW, ph = __expf(__ldg(xp+3*FSQ))*AH;
      float px = (float)(cell % 19) + sigf_(__ldg(xp));
      float py = (float)(cell / 19) + sigf_(__ldg(xp+FSQ));
      float hw = 0.5f*pw, hh = 0.5f*ph;
      c.plx[k] = px-hw; c.phx[k] = px+hw; c.ply[k] = py-hh; c.phy[k] = py+hh;
      c.ap3[k] = pw*ph*(1.0f/3.0f);
    }
  }
}

__device__ __forceinline__ void main_post2(int b, const Ctx2& c, int nv, int hm,
    const float4* s_box, const float* s_ar3, float* acc){
  constexpr int FSQ = FSQ2;
  bool un[4] = {false,false,false,false};
  #pragma unroll
  for (int k = 0; k < 4; k++){
    int cc = c.base + k*TPB;
    if (cc < 3*FSQ){
      int m = g_cm[CMOFF2 + b*3*FSQ + cc];
      if (m){ acc[2] += -clogf_(c.so[k]); float e = c.so[k]-1.f; acc[4] += e*e; }
      else un[k] = true;
    }
  }
  float vmax[4] = {-1e30f,-1e30f,-1e30f,-1e30f};
  if (hm){
    for (int t = 0; t < nv; t++){
      float4 tb = s_box[t];
      float ar3 = s_ar3[t];
      #pragma unroll
      for (int k = 0; k < 4; k++){
        float wi = fmaxf(fminf(c.phx[k], tb.z) - fmaxf(c.plx[k], tb.x), 0.f);
        float hi = fminf(c.phy[k], tb.w) - fmaxf(c.ply[k], tb.y);
        vmax[k] = fmaxf(vmax[k], fmaf(wi, hi, -ar3));
      }
    }
  }
  #pragma unroll
  for (int k = 0; k < 4; k++){
    if (un[k] && !(vmax[k] > c.ap3[k])){ acc[2] += -clogf_(1.f - c.so[k]); acc[4] += c.so[k]*c.so[k]; }
  }
}

// ------------------------------------------------------------------ THE kernel
__global__ __launch_bounds__(TPB, 4) void k_all(
    const float* __restrict__ x0, const float* __restrict__ x1, const float* __restrict__ x2,
    const float* __restrict__ labels, float* __restrict__ gout)
{
  __shared__ float4 s_box[NT];
  __shared__ float  s_ar3[NT];
  __shared__ float  s_red[5];
  __shared__ int    s_nv, s_hm;
  int bid = blockIdx.x, tid = threadIdx.x;
  if (tid < 5) s_red[tid] = 0.f;
  float acc[5] = {0.f,0.f,0.f,0.f,0.f};

  if (bid == 0){
    // ================= PREP BLOCK =================
    if (tid < 6) gout[tid] = 0.0f;
    if (tid == 0) g_nmatch = 0;
    // phase 1: 960 items over 256 threads
    for (int idx = tid; idx < NB*NT; idx += TPB){
      int b = idx / NT, t = idx - b*NT;
      const float* lp = labels + idx*5;
      float a0 = lp[0], a1 = lp[1], a2 = lp[2], a3 = lp[3], a4 = lp[4];
      bool valid = (a0+a1+a2+a3+a4) > 0.0f;
      g_validf[idx] = valid ? 1 : 0;
      int bi = 0;
      if (valid){
        float tw = (a2-a0)*0.125f, th = (a3-a1)*0.125f;   // L0 scale; ciou scale-invariant
        float at_t = atanf(tw/th);
        float twth = tw*th;
        float best = -3.0e38f;
        #pragma unroll
        for (int k = 0; k < 9; k++){
          float wb = cANW[k]*0.125f, hb = cANH[k]*0.125f;
          float ai = fminf(tw,wb)*fminf(th,hb);
          float au = twth + wb*hb - ai;
          float iou = ai/au;
          float mw = fmaxf(tw,wb), mh = fmaxf(th,hb);
          float c2 = mw*mw + mh*mh + 1e-16f;
          float dw = tw-wb, dh = th-hb;
          float rho2 = (dw*dw + dh*dh)*0.25f;
          float da = at_t - cATAN[k];
          float v = 0.40528473455296503f*(da*da);    // 4/pi^2
          float alpha = v/(1.0f - iou + v);
          float ciou = iou - (rho2/c2 + v*alpha);
          if (ciou > best){ best = ciou; bi = k; }   // first-max == jnp.argmax
        }
      }
      const float invsArr[3] = {0.125f, 0.0625f, 0.03125f};
      const int   fsArr[3]   = {76, 38, 19};
      #pragma unroll
      for (int L = 0; L < 3; L++){
        float invs = invsArr[L];
        int   fs   = fsArr[L];
        float tx = (a2+a0)*(0.5f*invs);   // exact: power-of-two scale
        float ty = (a3+a1)*(0.5f*invs);
        float tw = (a2-a0)*invs;
        float th = (a3-a1)*invs;
        float4 tb; float ar;
        if (valid){
          tb = make_float4(tx - tw*0.5f, ty - th*0.5f, tx + tw*0.5f, ty + th*0.5f);
          ar = tw*th;
        } else { tb = make_float4(0.f,0.f,0.f,0.f); ar = 0.f; }
        g_tbox[L][b][t]   = tb;
        g_tarea3[L][b][t] = ar*(1.0f/3.0f);
        int mi = -1;
        if (valid && (bi/3 == L)){
          int ii = (int)tx; ii = ii < 0 ? 0 : (ii > fs-1 ? fs-1 : ii);
          int jj = (int)ty; jj = jj < 0 ? 0 : (jj > fs-1 ? fs-1 : jj);
          mi = (bi - 3*L)*fs*fs + jj*fs + ii;
        }
        g_minfo[L][b][t] = mi;
      }
    }
    __syncthreads();
    // phase 2: 48 tasks over 8 warps
    int wid = tid >> 5, lane = tid & 31;
    unsigned lt = (1u << lane) - 1u;
    for (int task = wid; task < 48; task += 8){
      int L = task >> 4, b = task & 15;
      const int offA[3] = {0, CMOFF1, CMOFF2};
      const int n3A[3]  = {NC0, NC1, NC2};
      int base = offA[L] + b*n3A[L];
      int tA = lane, tB = lane + 32;
      int vA = g_validf[b*NT+tA];
      int vB = (tB < NT) ? g_validf[b*NT+tB] : 0;
      int miA = g_minfo[L][b][tA];
      int miB = (tB < NT) ? g_minfo[L][b][tB] : -1;
      unsigned mA  = __ballot_sync(~0u, vA != 0);
      unsigned mBv = __ballot_sync(~0u, vB != 0);
      int nA = __popc(mA);
      if (vA){ int p = __popc(mA & lt);       g_cbox[L][b][p] = g_tbox[L][b][tA]; g_car3[L][b][p] = g_tarea3[L][b][tA]; }
      if (vB){ int p = nA + __popc(mBv & lt); g_cbox[L][b][p] = g_tbox[L][b][tB]; g_car3[L][b][p] = g_tarea3[L][b][tB]; }
      int nv = nA + __popc(mBv);
      if (miA >= 0) atomicMax(&g_cm[base+miA], tA+1);      // last(max-t)-wins scatter
      if (miB >= 0) atomicMax(&g_cm[base+miB], tB+1);
      __syncwarp();
      bool wA = (miA >= 0) && (atomicMax(&g_cm[base+miA], 0) == tA+1);
      bool wB = (miB >= 0) && (atomicMax(&g_cm[base+miB], 0) == tB+1);
      unsigned mwA = __ballot_sync(~0u, wA);
      unsigned mwB = __ballot_sync(~0u, wB);
      int tot = __popc(mwA) + __popc(mwB);
      int slot0 = 0;
      if (lane == 0 && tot) slot0 = atomicAdd(&g_nmatch, tot);
      slot0 = __shfl_sync(~0u, slot0, 0);
      if (wA) g_mlist[slot0 + __popc(mwA & lt)]               = make_int2((L<<28)|(b<<24)|miA, tA);
      if (wB) g_mlist[slot0 + __popc(mwA) + __popc(mwB & lt)] = make_int2((L<<28)|(b<<24)|miB, tB);
      unsigned hmA = __ballot_sync(~0u, miA >= 0);
      unsigned hmB = __ballot_sync(~0u, miB >= 0);
      if (lane == 0){ g_cnv[L][b] = nv; g_hm[L][b] = ((hmA|hmB) != 0) ? 1 : 0; }
    }
    __threadfence();
    __syncthreads();
    if (tid == 0) atomicExch(&g_flag, 1);       // release
  } else if (bid <= MB){
    // ================= MATCH BLOCKS =================
    waitflag();
    int lane = tid & 31;
    int wbase = (bid-1)*8 + (tid >> 5);
    int nm = g_nmatch;
    #pragma unroll
    for (int rep = 0; rep < 2; rep++){
      int w = wbase + rep*(MB*8);
      if (w >= nm) break;
      int2 e = g_mlist[w];
      int code = e.x, t = e.y;
      int L = code >> 28, b = (code >> 24) & 0xF, cc = code & 0xFFFFFF;
      const int   fsqA[3]  = {FSQ0, FSQ1, FSQ2};
      const float invsA[3] = {0.125f, 0.0625f, 0.03125f};
      const float* x = (L==0) ? x0 : ((L==1) ? x1 : x2);
      int FSQ = fsqA[L];
      float invs = invsA[L];
      int a = cc/FSQ, cell = cc - a*FSQ;
      const float* xp = x + (b*255 + a*85)*FSQ + cell;
      const float* lp = labels + (b*NT + t)*5;
      float a0 = __ldg(lp), a1 = __ldg(lp+1), a2 = __ldg(lp+2), a3 = __ldg(lp+3), a4 = __ldg(lp+4);
      float tx = (a2+a0)*(0.5f*invs), ty = (a3+a1)*(0.5f*invs);
      float tw = (a2-a0)*invs,        th = (a3-a1)*invs;
      float scl = sqrtf(2.0f - tw*th/(float)FSQ);
      int cl = (int)a4;
      for (int c = lane; c < NCLS; c += 32){
        float s = sigf_(__ldg(xp + (5+c)*FSQ));
        if (c == cl){ acc[3] += -clogf_(s);       float er = s-1.f; acc[4] += er*er; }
        else        { acc[3] += -clogf_(1.f - s); acc[4] += s*s; }
      }
      if (lane == 0){
        float AW = cANW[3*L+a]*invs, AH = cANH[3*L+a]*invs;
        float o0 = __ldg(xp), o1 = __ldg(xp+FSQ), o2 = __ldg(xp+2*FSQ), o3 = __ldg(xp+3*FSQ);
        float s0 = sigf_(o0), s1 = sigf_(o1);
        float fx = tx - truncf(tx), fy = ty - truncf(ty);
        float lw = __logf(tw/AW + 1e-16f), lh = __logf(th/AH + 1e-16f);
        float w2 = scl*scl;
        acc[0] += w2*( -(fx*clogf_(s0) + (1.f-fx)*clogf_(1.f-s0))
                       -(fy*clogf_(s1) + (1.f-fy)*clogf_(1.f-s1)) );
        float dx = (o2-lw)*scl, dy = (o3-lh)*scl;
        acc[1] += 0.5f*(dx*dx + dy*dy);
        float e0 = s0-fx, e1 = s1-fy;
        acc[4] += e0*e0 + e1*e1 + dx*dx + dy*dy;
      }
    }
  } else {
    // ================= MAIN BLOCKS =================
    int mbid = bid - 1 - MB;
    int Lv, b, chunk;
    if (mbid < NB*CH0)            { Lv = 0; b = mbid/CH0;                    chunk = mbid - b*CH0; }
    else if (mbid < NB*(CH0+CH1)) { int r = mbid - NB*CH0;       Lv = 1; b = r/CH1; chunk = r - b*CH1; }
    else                          { int r = mbid - NB*(CH0+CH1); Lv = 2; b = r/CH2; chunk = r - b*CH2; }
    if (Lv == 0){
      Ctx<0,76> c; main_pre<0,76>(x0, b, chunk, c);
      waitflag();
      if (tid < NT){ s_box[tid] = g_cbox[0][b][tid]; s_ar3[tid] = g_car3[0][b][tid]; }
      if (tid == 0){ s_nv = g_cnv[0][b]; s_hm = g_hm[0][b]; }
      __syncthreads();
      main_post<0,76,0>(b, c, s_nv, s_hm, s_box, s_ar3, acc);
    } else if (Lv == 1){
      Ctx<1,38> c; main_pre<1,38>(x1, b, chunk, c);
      waitflag();
      if (tid < NT){ s_box[tid] = g_cbox[1][b][tid]; s_ar3[tid] = g_car3[1][b][tid]; }
      if (tid == 0){ s_nv = g_cnv[1][b]; s_hm = g_hm[1][b]; }
      __syncthreads();
      main_post<1,38,CMOFF1>(b, c, s_nv, s_hm, s_box, s_ar3, acc);
    } else {
      Ctx2 c; main_pre2(x2, b, chunk, c);
      waitflag();
      if (tid < NT){ s_box[tid] = g_cbox[2][b][tid]; s_ar3[tid] = g_car3[2][b][tid]; }
      if (tid == 0){ s_nv = g_cnv[2][b]; s_hm = g_hm[2][b]; }
      __syncthreads();
      main_post2(b, c, s_nv, s_hm, s_box, s_ar3, acc);
    }
  }

  // ================= reduction =================
  #pragma unroll
  for (int k = 0; k < 5; k++){
    float v = acc[k];
    #pragma unroll
    for (int off = 16; off > 0; off >>= 1) v += __shfl_down_sync(0xffffffffu, v, off);
    if ((tid & 31) == 0 && v != 0.f) atomicAdd(&s_red[k], v);
  }
  __syncthreads();
  if (tid < 5 && s_red[tid] != 0.f) atomicAdd(&gout[1+tid], s_red[tid]);

  __threadfence();
  __syncthreads();
  if (tid == 0){
    if (atomicAdd(&g_done, 1) == GRID-1){
      g_done = 0;                                  // restore invariants for next replay
      g_flag = 0;
      float l1 = atomicAdd(&gout[1], 0.f);
      float l2 = atomicAdd(&gout[2], 0.f);
      float l3 = atomicAdd(&gout[3], 0.f);
      float l4 = atomicAdd(&gout[4], 0.f);
      gout[0] = l1+l2+l3+l4;
    }
  }
}

// ------------------------------------------------------------------ launch
extern "C" void kernel_launch(void* const* d_in, const int* in_sizes, int n_in,
                              void* d_out, int out_size)
{
  const float* x0     = (const float*)d_in[0];
  const float* x1     = (const float*)d_in[1];
  const float* x2     = (const float*)d_in[2];
  const float* labels = (const float*)d_in[3];
  float* gout = (float*)d_out;
  (void)in_sizes; (void)n_in; (void)out_size;

  k_all<<<GRID, TPB>>>(x0, x1, x2, labels, gout);
}

// round 9
// speedup vs baseline: 1.2176x; 1.2176x over previous
#include <cuda_runtime.h>
#include <math.h>

#define NB 16
#define NT 60
#define NCLS 80

__constant__ float cANW[9] = {12.f,19.f,40.f,36.f,76.f,72.f,142.f,192.f,459.f};
__constant__ float cANH[9] = {16.f,36.f,28.f,75.f,55.f,146.f,110.f,243.f,401.f};
// atan(w/h) per anchor — scale-invariant constants (<5e-6 abs err; argmax gaps O(1e-2))
__constant__ float cATAN[9] = {0.6435011f, 0.4856221f, 0.9600704f,
                               0.4475200f, 0.9443511f, 0.4581533f,
                               0.9117062f, 0.6686896f, 0.8527381f};

#define FSQ0 5776
#define FSQ1 1444
#define FSQ2 361
#define NC0 (3*FSQ0)
#define NC1 (3*FSQ1)
#define NC2 (3*FSQ2)
#define CMOFF1 (NB*NC0)
#define CMOFF2 (CMOFF1+NB*NC1)
#define NCM    (CMOFF2+NB*NC2)

#define TPB 256
#define CELLS 1024
#define CH0 17
#define CH1 5
#define CH2 2
#define MB 60
#define MAINB (NB*(CH0+CH1+CH2))   /* 384 */
#define GRID (MB+MAINB)            /* 444 */

__device__ float4 g_tbox[3][NB][NT];      // corner form: (tlx, tly, brx, bry)
__device__ float  g_tarea3[3][NB][NT];    // tw*th/3
__device__ int    g_minfo[3][NB][NT];
__device__ int    g_validf[NB*NT];
__device__ float4 g_cbox[3][NB][NT];      // compacted, corner form
__device__ float  g_car3[3][NB][NT];
__device__ int    g_cnv[3][NB];
__device__ int    g_hm[3][NB];
__device__ __align__(16) int g_cm[NCM];   // monotone via atomicMax; replay-idempotent
__device__ int    g_nmatch;
__device__ int2   g_mlist[NB*NT];
__device__ int    g_done;

__device__ __forceinline__ float clogf_(float v){ return fmaxf(__logf(v), -100.0f); }
__device__ __forceinline__ float sigf_(float v){ return __fdividef(1.0f, 1.0f + __expf(-v)); }

// ------------------------------------------------------------------ prep (ONE 960-thread block; PDL primary)
// NOTE: no explicit cudaTriggerProgrammaticLaunchCompletion(). The implicit
// trigger fires at kernel COMPLETION, so the secondary's
// cudaGridDependencySynchronize() guarantees full visibility of all prep
// writes. The secondary still overlaps its pre-sync work with this kernel.
__global__ __launch_bounds__(960) void k_prep(const float* __restrict__ labels, float* __restrict__ gout){
  int idx = threadIdx.x;
  if (idx < 6) gout[idx] = 0.0f;
  if (idx == 0) g_nmatch = 0;

  // ---- phase 1: per-(b,t) boxes + scale-invariant CIoU argmax (once) ----
  {
    int b = idx / NT, t = idx - b*NT;
    const float* lp = labels + idx*5;
    float a0 = lp[0], a1 = lp[1], a2 = lp[2], a3 = lp[3], a4 = lp[4];
    bool valid = (a0+a1+a2+a3+a4) > 0.0f;
    g_validf[idx] = valid ? 1 : 0;
    int bi = 0;
    if (valid){
      float tw = (a2-a0)*0.125f, th = (a3-a1)*0.125f;   // L0 scale; ciou scale-invariant
      float at_t = atanf(tw/th);
      float twth = tw*th;
      float best = -3.0e38f;
      #pragma unroll
      for (int k = 0; k < 9; k++){
        float wb = cANW[k]*0.125f, hb = cANH[k]*0.125f;
        float ai = fminf(tw,wb)*fminf(th,hb);
        float au = twth + wb*hb - ai;
        float iou = ai/au;
        float mw = fmaxf(tw,wb), mh = fmaxf(th,hb);
        float c2 = mw*mw + mh*mh + 1e-16f;
        float dw = tw-wb, dh = th-hb;
        float rho2 = (dw*dw + dh*dh)*0.25f;
        float da = at_t - cATAN[k];
        float v = 0.40528473455296503f*(da*da);    // 4/pi^2
        float alpha = v/(1.0f - iou + v);
        float ciou = iou - (rho2/c2 + v*alpha);
        if (ciou > best){ best = ciou; bi = k; }   // first-max == jnp.argmax
      }
    }
    const float invsArr[3] = {0.125f, 0.0625f, 0.03125f};
    const int   fsArr[3]   = {76, 38, 19};
    #pragma unroll
    for (int L = 0; L < 3; L++){
      float invs = invsArr[L];
      int   fs   = fsArr[L];
      float tx = (a2+a0)*(0.5f*invs);   // exact: power-of-two scale
      float ty = (a3+a1)*(0.5f*invs);
      float tw = (a2-a0)*invs;
      float th = (a3-a1)*invs;
      float4 tb; float ar;
      if (valid){
        tb = make_float4(tx - tw*0.5f, ty - th*0.5f, tx + tw*0.5f, ty + th*0.5f);
        ar = tw*th;
      } else { tb = make_float4(0.f,0.f,0.f,0.f); ar = 0.f; }
      g_tbox[L][b][t]   = tb;
      g_tarea3[L][b][t] = ar*(1.0f/3.0f);
      int mi = -1;
      if (valid && (bi/3 == L)){
        int ii = (int)tx; ii = ii < 0 ? 0 : (ii > fs-1 ? fs-1 : ii);
        int jj = (int)ty; jj = jj < 0 ? 0 : (jj > fs-1 ? fs-1 : jj);
        mi = (bi - 3*L)*fs*fs + jj*fs + ii;
      }
      g_minfo[L][b][t] = mi;
    }
  }
  __syncthreads();

  // ---- phase 2: one warp per (L,b) task, 48 tasks over 30 warps ----
  int wid = idx >> 5, lane = idx & 31;
  unsigned lt = (1u << lane) - 1u;
  for (int task = wid; task < 48; task += 30){
    int L = task >> 4, b = task & 15;
    const int offA[3] = {0, CMOFF1, CMOFF2};
    const int n3A[3]  = {NC0, NC1, NC2};
    int base = offA[L] + b*n3A[L];
    int tA = lane, tB = lane + 32;
    int vA = g_validf[b*NT+tA];
    int vB = (tB < NT) ? g_validf[b*NT+tB] : 0;
    int miA = g_minfo[L][b][tA];
    int miB = (tB < NT) ? g_minfo[L][b][tB] : -1;
    unsigned mA  = __ballot_sync(~0u, vA != 0);
    unsigned mBv = __ballot_sync(~0u, vB != 0);
    int nA = __popc(mA);
    if (vA){ int p = __popc(mA & lt);       g_cbox[L][b][p] = g_tbox[L][b][tA]; g_car3[L][b][p] = g_tarea3[L][b][tA]; }
    if (vB){ int p = nA + __popc(mBv & lt); g_cbox[L][b][p] = g_tbox[L][b][tB]; g_car3[L][b][p] = g_tarea3[L][b][tB]; }
    int nv = nA + __popc(mBv);
    if (miA >= 0) atomicMax(&g_cm[base+miA], tA+1);      // last(max-t)-wins scatter
    if (miB >= 0) atomicMax(&g_cm[base+miB], tB+1);
    __syncwarp();
    bool wA = (miA >= 0) && (atomicMax(&g_cm[base+miA], 0) == tA+1);
    bool wB = (miB >= 0) && (atomicMax(&g_cm[base+miB], 0) == tB+1);
    unsigned mwA = __ballot_sync(~0u, wA);
    unsigned mwB = __ballot_sync(~0u, wB);
    int tot = __popc(mwA) + __popc(mwB);
    int slot0 = 0;
    if (lane == 0 && tot) slot0 = atomicAdd(&g_nmatch, tot);
    slot0 = __shfl_sync(~0u, slot0, 0);
    if (wA) g_mlist[slot0 + __popc(mwA & lt)]               = make_int2((L<<28)|(b<<24)|miA, tA);
    if (wB) g_mlist[slot0 + __popc(mwA) + __popc(mwB & lt)] = make_int2((L<<28)|(b<<24)|miB, tB);
    unsigned hmA = __ballot_sync(~0u, miA >= 0);
    unsigned hmB = __ballot_sync(~0u, miB >= 0);
    if (lane == 0){ g_cnv[L][b] = nv; g_hm[L][b] = ((hmA|hmB) != 0) ? 1 : 0; }
  }
}

// ------------------------------------------------------------------ per-thread main context (prep-independent part)
template<int L, int FS>
struct Ctx {
  float so[4], plx[4], ply[4], phx[4], phy[4], ap3[4];
  int base;
};

template<int L, int FS>
__device__ __forceinline__ void main_pre(const float* __restrict__ x, int b, int chunk, Ctx<L,FS>& c){
  constexpr int FSQ = FS*FS;
  constexpr float invs = (L==0) ? 0.125f : 0.0625f;
  c.base = chunk*CELLS + (int)threadIdx.x*4;
  #pragma unroll
  for (int k = 0; k < 4; k++){
    c.so[k] = 0.f; c.plx[k] = 3e4f; c.phx[k] = 3e4f; c.ply[k] = 0.f; c.phy[k] = 0.f; c.ap3[k] = 1.f;
  }
  if (c.base < 3*FSQ){
    int a = c.base/FSQ, cell = c.base - a*FSQ;
    int j0 = cell / FS, i0 = cell - j0*FS;            // FS%4==0 => 4 cells share a row
    const float* xp = x + (b*255 + a*85)*FSQ + cell;
    float4 O0 = __ldg((const float4*)(xp));
    float4 O1 = __ldg((const float4*)(xp+FSQ));
    float4 O2 = __ldg((const float4*)(xp+2*FSQ));
    float4 O3 = __ldg((const float4*)(xp+3*FSQ));
    float4 O4 = __ldg((const float4*)(xp+4*FSQ));
    float AW = cANW[3*L+a]*invs, AH = cANH[3*L+a]*invs;
    float o0a[4] = {O0.x,O0.y,O0.z,O0.w};
    float o1a[4] = {O1.x,O1.y,O1.z,O1.w};
    float o2a[4] = {O2.x,O2.y,O2.z,O2.w};
    float o3a[4] = {O3.x,O3.y,O3.z,O3.w};
    float o4a[4] = {O4.x,O4.y,O4.z,O4.w};
    float fj = (float)j0;
    #pragma unroll
    for (int k = 0; k < 4; k++){
      c.so[k] = sigf_(o4a[k]);
      float pw = __expf(o2a[k])*AW, ph = __expf(o3a[k])*AH;
      float px = (float)(i0+k) + sigf_(o0a[k]);
      float py = fj + sigf_(o1a[k]);
      float hw = 0.5f*pw, hh = 0.5f*ph;
      c.plx[k] = px-hw; c.phx[k] = px+hw; c.ply[k] = py-hh; c.phy[k] = py+hh;
      c.ap3[k] = pw*ph*(1.0f/3.0f);
    }
  }
}

template<int L, int FS, int CMOFF>
__device__ __forceinline__ void main_post(int b, const Ctx<L,FS>& c, int nv, int hm,
    const float4* s_box, const float* s_ar3, float* acc){
  constexpr int FSQ = FS*FS;
  bool un[4] = {false,false,false,false};
  if (c.base < 3*FSQ){
    int4 CM = *(const int4*)&g_cm[CMOFF + b*3*FSQ + c.base];
    int cma[4] = {CM.x,CM.y,CM.z,CM.w};
    #pragma unroll
    for (int k = 0; k < 4; k++){
      if (cma[k]){ acc[2] += -clogf_(c.so[k]); float e = c.so[k]-1.f; acc[4] += e*e; }
      else un[k] = true;
    }
  }
  float vmax[4] = {-1e30f,-1e30f,-1e30f,-1e30f};
  if (hm){
    #pragma unroll 2
    for (int t = 0; t < nv; t++){
      float4 tb = s_box[t];
      float ar3 = s_ar3[t];
      #pragma unroll
      for (int k = 0; k < 4; k++){
        float wi = fmaxf(fminf(c.phx[k], tb.z) - fmaxf(c.plx[k], tb.x), 0.f);
        float hi = fminf(c.phy[k], tb.w) - fmaxf(c.ply[k], tb.y);
        vmax[k] = fmaxf(vmax[k], fmaf(wi, hi, -ar3));   // iou>.5 <=> ai-at/3 > ap/3
      }
    }
  }
  #pragma unroll
  for (int k = 0; k < 4; k++){
    if (un[k] && !(vmax[k] > c.ap3[k])){ acc[2] += -clogf_(1.f - c.so[k]); acc[4] += c.so[k]*c.so[k]; }
  }
}

// scalar variant for L2 (FSQ=361, not divisible by 4)
struct Ctx2 {
  float so[4], plx[4], ply[4], phx[4], phy[4], ap3[4];
  int base;
};

__device__ __forceinline__ void main_pre2(const float* __restrict__ x, int b, int chunk, Ctx2& c){
  constexpr int FSQ = FSQ2;
  constexpr float invs = 0.03125f;
  c.base = chunk*CELLS + (int)threadIdx.x;
  #pragma unroll
  for (int k = 0; k < 4; k++){
    int cc = c.base + k*TPB;
    c.so[k] = 0.f; c.plx[k] = 3e4f; c.phx[k] = 3e4f; c.ply[k] = 0.f; c.phy[k] = 0.f; c.ap3[k] = 1.f;
    if (cc < 3*FSQ){
      int a = cc/FSQ, cell = cc - a*FSQ;
      const float* xp = x + (b*255 + a*85)*FSQ + cell;
      c.so[k] = sigf_(__ldg(xp + 4*FSQ));
      float AW = cANW[6+a]*invs, AH = cANH[6+a]*invs;
      float pw = __expf(__ldg(xp+2*FSQ))*AW, ph = __expf(__ldg(xp+3*FSQ))*AH;
      float px = (float)(cell % 19) + sigf_(__ldg(xp));
      float py = (float)(cell / 19) + sigf_(__ldg(xp+FSQ));
      float hw = 0.5f*pw, hh = 0.5f*ph;
      c.plx[k] = px-hw; c.phx[k] = px+hw; c.ply[k] = py-hh; c.phy[k] = py+hh;
      c.ap3[k] = pw*ph*(1.0f/3.0f);
    }
  }
}

__device__ __forceinline__ void main_post2(int b, const Ctx2& c, int nv, int hm,
    const float4* s_box, const float* s_ar3, float* acc){
  constexpr int FSQ = FSQ2;
  bool un[4] = {false,false,false,false};
  #pragma unroll
  for (int k = 0; k < 4; k++){
    int cc = c.base + k*TPB;
    if (cc < 3*FSQ){
      int m = g_cm[CMOFF2 + b*3*FSQ + cc];
      if (m){ acc[2] += -clogf_(c.so[k]); float e = c.so[k]-1.f; acc[4] += e*e; }
      else un[k] = true;
    }
  }
  float vmax[4] = {-1e30f,-1e30f,-1e30f,-1e30f};
  if (hm){
    for (int t = 0; t < nv; t++){
      float4 tb = s_box[t];
      float ar3 = s_ar3[t];
      #pragma unroll
      for (int k = 0; k < 4; k++){
        float wi = fmaxf(fminf(c.phx[k], tb.z) - fmaxf(c.plx[k], tb.x), 0.f);
        float hi = fminf(c.phy[k], tb.w) - fmaxf(c.ply[k], tb.y);
        vmax[k] = fmaxf(vmax[k], fmaf(wi, hi, -ar3));
      }
    }
  }
  #pragma unroll
  for (int k = 0; k < 4; k++){
    if (un[k] && !(vmax[k] > c.ap3[k])){ acc[2] += -clogf_(1.f - c.so[k]); acc[4] += c.so[k]*c.so[k]; }
  }
}

// ------------------------------------------------------------------ big kernel (PDL secondary)
__global__ __launch_bounds__(TPB) void k_big(
    const float* __restrict__ x0, const float* __restrict__ x1, const float* __restrict__ x2,
    const float* __restrict__ labels, float* __restrict__ gout)
{
  __shared__ float4 s_box[NT];
  __shared__ float  s_ar3[NT];
  __shared__ float  s_red[5];
  __shared__ int    s_nv, s_hm;
  int bid = blockIdx.x, tid = threadIdx.x;
  if (tid < 5) s_red[tid] = 0.f;
  float acc[5] = {0.f,0.f,0.f,0.f,0.f};

  if (bid < MB){
    // ---------------- match blocks: nothing useful pre-sync ----------------
    cudaGridDependencySynchronize();
    __syncthreads();
    int lane = tid & 31;
    int wbase = bid*8 + (tid >> 5);
    int nm = g_nmatch;
    #pragma unroll
    for (int rep = 0; rep < 2; rep++){
      int w = wbase + rep*(MB*8);
      if (w >= nm) break;
      int2 e = g_mlist[w];
      int code = e.x, t = e.y;
      int L = code >> 28, b = (code >> 24) & 0xF, cc = code & 0xFFFFFF;
      const int   fsqA[3]  = {FSQ0, FSQ1, FSQ2};
      const float invsA[3] = {0.125f, 0.0625f, 0.03125f};
      const float* x = (L==0) ? x0 : ((L==1) ? x1 : x2);
      int FSQ = fsqA[L];
      float invs = invsA[L];
      int a = cc/FSQ, cell = cc - a*FSQ;
      const float* xp = x + (b*255 + a*85)*FSQ + cell;
      const float* lp = labels + (b*NT + t)*5;
      float a0 = __ldg(lp), a1 = __ldg(lp+1), a2 = __ldg(lp+2), a3 = __ldg(lp+3), a4 = __ldg(lp+4);
      float tx = (a2+a0)*(0.5f*invs), ty = (a3+a1)*(0.5f*invs);
      float tw = (a2-a0)*invs,        th = (a3-a1)*invs;
      float scl = sqrtf(2.0f - tw*th/(float)FSQ);
      int cl = (int)a4;
      for (int c = lane; c < NCLS; c += 32){
        float s = sigf_(__ldg(xp + (5+c)*FSQ));
        if (c == cl){ acc[3] += -clogf_(s);       float er = s-1.f; acc[4] += er*er; }
        else        { acc[3] += -clogf_(1.f - s); acc[4] += s*s; }
      }
      if (lane == 0){
        float AW = cANW[3*L+a]*invs, AH = cANH[3*L+a]*invs;
        float o0 = __ldg(xp), o1 = __ldg(xp+FSQ), o2 = __ldg(xp+2*FSQ), o3 = __ldg(xp+3*FSQ);
        float s0 = sigf_(o0), s1 = sigf_(o1);
        float fx = tx - truncf(tx), fy = ty - truncf(ty);
        float lw = __logf(tw/AW + 1e-16f), lh = __logf(th/AH + 1e-16f);
        float w2 = scl*scl;
        acc[0] += w2*( -(fx*clogf_(s0) + (1.f-fx)*clogf_(1.f-s0))
                       -(fy*clogf_(s1) + (1.f-fy)*clogf_(1.f-s1)) );
        float dx = (o2-lw)*scl, dy = (o3-lh)*scl;
        acc[1] += 0.5f*(dx*dx + dy*dy);
        float e0 = s0-fx, e1 = s1-fy;
        acc[4] += e0*e0 + e1*e1 + dx*dx + dy*dy;
      }
    }
  } else {
    // ---------------- main blocks: precompute (overlaps prep), then sync ----------------
    int mbid = bid - MB;
    int Lv, b, chunk;
    if (mbid < NB*CH0)            { Lv = 0; b = mbid/CH0;                    chunk = mbid - b*CH0; }
    else if (mbid < NB*(CH0+CH1)) { int r = mbid - NB*CH0;       Lv = 1; b = r/CH1; chunk = r - b*CH1; }
    else                          { int r = mbid - NB*(CH0+CH1); Lv = 2; b = r/CH2; chunk = r - b*CH2; }
    if (Lv == 0){
      Ctx<0,76> c; main_pre<0,76>(x0, b, chunk, c);
      cudaGridDependencySynchronize();
      if (tid < NT){ s_box[tid] = g_cbox[0][b][tid]; s_ar3[tid] = g_car3[0][b][tid]; }
      if (tid == 0){ s_nv = g_cnv[0][b]; s_hm = g_hm[0][b]; }
      __syncthreads();
      main_post<0,76,0>(b, c, s_nv, s_hm, s_box, s_ar3, acc);
    } else if (Lv == 1){
      Ctx<1,38> c; main_pre<1,38>(x1, b, chunk, c);
      cudaGridDependencySynchronize();
      if (tid < NT){ s_box[tid] = g_cbox[1][b][tid]; s_ar3[tid] = g_car3[1][b][tid]; }
      if (tid == 0){ s_nv = g_cnv[1][b]; s_hm = g_hm[1][b]; }
      __syncthreads();
      main_post<1,38,CMOFF1>(b, c, s_nv, s_hm, s_box, s_ar3, acc);
    } else {
      Ctx2 c; main_pre2(x2, b, chunk, c);
      cudaGridDependencySynchronize();
      if (tid < NT){ s_box[tid] = g_cbox[2][b][tid]; s_ar3[tid] = g_car3[2][b][tid]; }
      if (tid == 0){ s_nv = g_cnv[2][b]; s_hm = g_hm[2][b]; }
      __syncthreads();
      main_post2(b, c, s_nv, s_hm, s_box, s_ar3, acc);
    }
  }

  // ---------------- reduction ----------------
  #pragma unroll
  for (int k = 0; k < 5; k++){
    float v = acc[k];
    #pragma unroll
    for (int off = 16; off > 0; off >>= 1) v += __shfl_down_sync(0xffffffffu, v, off);
    if ((tid & 31) == 0 && v != 0.f) atomicAdd(&s_red[k], v);
  }
  __syncthreads();
  if (tid < 5 && s_red[tid] != 0.f) atomicAdd(&gout[1+tid], s_red[tid]);

  __threadfence();
  __syncthreads();
  if (tid == 0){
    if (atomicAdd(&g_done, 1) == GRID-1){
      g_done = 0;                                  // restore invariant for next replay
      float l1 = atomicAdd(&gout[1], 0.f);
      float l2 = atomicAdd(&gout[2], 0.f);
      float l3 = atomicAdd(&gout[3], 0.f);
      float l4 = atomicAdd(&gout[4], 0.f);
      gout[0] = l1+l2+l3+l4;
    }
  }
}

// ------------------------------------------------------------------ launch (PDL-chained)
extern "C" void kernel_launch(void* const* d_in, const int* in_sizes, int n_in,
                              void* d_out, int out_size)
{
  const float* x0     = (const float*)d_in[0];
  const float* x1     = (const float*)d_in[1];
  const float* x2     = (const float*)d_in[2];
  const float* labels = (const float*)d_in[3];
  float* gout = (float*)d_out;
  (void)in_sizes; (void)n_in; (void)out_size;

  k_prep<<<1, 960>>>(labels, gout);

  cudaLaunchConfig_t cfg = {};
  cfg.gridDim  = dim3(GRID, 1, 1);
  cfg.blockDim = dim3(TPB, 1, 1);
  cfg.dynamicSmemBytes = 0;
  cfg.stream = 0;
  cudaLaunchAttribute attrs[1];
  attrs[0].id = cudaLaunchAttributeProgrammaticStreamSerialization;
  attrs[0].val.programmaticStreamSerializationAllowed = 1;
  cfg.attrs = attrs;
  cfg.numAttrs = 1;
  cudaLaunchKernelEx(&cfg, k_big, x0, x1, x2, labels, gout);
}

// round 10
// speedup vs baseline: 1.3433x; 1.1032x over previous
#include <cuda_runtime.h>
#include <math.h>

#define NB 16
#define NT 60
#define NCLS 80

__constant__ float cANW[9] = {12.f,19.f,40.f,36.f,76.f,72.f,142.f,192.f,459.f};
__constant__ float cANH[9] = {16.f,36.f,28.f,75.f,55.f,146.f,110.f,243.f,401.f};
// atan(w/h) per anchor — scale-invariant constants (<5e-6 abs err; argmax gaps O(1e-2))
__constant__ float cATAN[9] = {0.6435011f, 0.4856221f, 0.9600704f,
                               0.4475200f, 0.9443511f, 0.4581533f,
                               0.9117062f, 0.6686896f, 0.8527381f};

#define FSQ0 5776
#define FSQ1 1444
#define FSQ2 361

#define TPB 256
#define CELLS 1024
#define CH0 17
#define CH1 5
#define CH2 2
#define MATCHB 16                    /* one match block per batch b */
#define MAINB (NB*(CH0+CH1+CH2))     /* 384 */
#define GRID (MATCHB + MAINB)        /* 400 */

__device__ float g_partial[GRID][5]; // fully rewritten each run — replay safe
__device__ int   g_done;             // reset to 0 by last block each run

__device__ __forceinline__ float clogf_(float v){ return fmaxf(__logf(v), -100.0f); }
__device__ __forceinline__ float sigf_(float v){ return __fdividef(1.0f, 1.0f + __expf(-v)); }

// CIoU argmax over 9 anchors at L0 scale (scale-invariant across levels)
__device__ __forceinline__ int ciou_argmax(float tw, float th){
  float at_t = atanf(tw/th);
  float twth = tw*th;
  float best = -3.0e38f; int bi = 0;
  #pragma unroll
  for (int k = 0; k < 9; k++){
    float wb = cANW[k]*0.125f, hb = cANH[k]*0.125f;
    float ai = fminf(tw,wb)*fminf(th,hb);
    float au = twth + wb*hb - ai;
    float iou = ai/au;
    float mw = fmaxf(tw,wb), mh = fmaxf(th,hb);
    float c2 = mw*mw + mh*mh + 1e-16f;
    float dw = tw-wb, dh = th-hb;
    float rho2 = (dw*dw + dh*dh)*0.25f;
    float da = at_t - cATAN[k];
    float v = 0.40528473455296503f*(da*da);      // 4/pi^2
    float alpha = v/(1.0f - iou + v);
    float ciou = iou - (rho2/c2 + v*alpha);
    if (ciou > best){ best = ciou; bi = k; }     // first-max == jnp.argmax
  }
  return bi;
}

// ------------------------------------------------------------------ main-path context (proven corner form)
template<int L, int FS>
struct Ctx {
  float so[4], plx[4], ply[4], phx[4], phy[4], ap3[4];
  int base;
};

template<int L, int FS>
__device__ __forceinline__ void main_pre(const float* __restrict__ x, int b, int chunk, Ctx<L,FS>& c){
  constexpr int FSQ = FS*FS;
  constexpr float invs = (L==0) ? 0.125f : 0.0625f;
  c.base = chunk*CELLS + (int)threadIdx.x*4;
  #pragma unroll
  for (int k = 0; k < 4; k++){
    c.so[k] = 0.f; c.plx[k] = 3e4f; c.phx[k] = 3e4f; c.ply[k] = 0.f; c.phy[k] = 0.f; c.ap3[k] = 1.f;
  }
  if (c.base < 3*FSQ){
    int a = c.base/FSQ, cell = c.base - a*FSQ;
    int j0 = cell / FS, i0 = cell - j0*FS;       // FS%4==0 => 4 cells share a row
    const float* xp = x + (b*255 + a*85)*FSQ + cell;
    float4 O0 = __ldg((const float4*)(xp));
    float4 O1 = __ldg((const float4*)(xp+FSQ));
    float4 O2 = __ldg((const float4*)(xp+2*FSQ));
    float4 O3 = __ldg((const float4*)(xp+3*FSQ));
    float4 O4 = __ldg((const float4*)(xp+4*FSQ));
    float AW = cANW[3*L+a]*invs, AH = cANH[3*L+a]*invs;
    float o0a[4] = {O0.x,O0.y,O0.z,O0.w};
    float o1a[4] = {O1.x,O1.y,O1.z,O1.w};
    float o2a[4] = {O2.x,O2.y,O2.z,O2.w};
    float o3a[4] = {O3.x,O3.y,O3.z,O3.w};
    float o4a[4] = {O4.x,O4.y,O4.z,O4.w};
    float fj = (float)j0;
    #pragma unroll
    for (int k = 0; k < 4; k++){
      c.so[k] = sigf_(o4a[k]);
      float pw = __expf(o2a[k])*AW, ph = __expf(o3a[k])*AH;
      float px = (float)(i0+k) + sigf_(o0a[k]);
      float py = fj + sigf_(o1a[k]);
      float hw = 0.5f*pw, hh = 0.5f*ph;
      c.plx[k] = px-hw; c.phx[k] = px+hw; c.ply[k] = py-hh; c.phy[k] = py+hh;
      c.ap3[k] = pw*ph*(1.0f/3.0f);
    }
  }
}

template<int L, int FS>
__device__ __forceinline__ void main_post(const Ctx<L,FS>& c, int nv, int hm,
    const float4* s_box, const float* s_ar3, const unsigned char* s_mbit, float* acc){
  constexpr int FSQ = FS*FS;
  bool un[4] = {false,false,false,false};
  if (c.base < 3*FSQ){
    uchar4 mb = *(const uchar4*)(s_mbit + threadIdx.x*4);  // in-chunk offset = tid*4
    unsigned char m[4] = {mb.x, mb.y, mb.z, mb.w};
    #pragma unroll
    for (int k = 0; k < 4; k++){
      if (m[k]){ acc[2] += -clogf_(c.so[k]); float e = c.so[k]-1.f; acc[4] += e*e; }
      else un[k] = true;
    }
  }
  float vmax[4] = {-1e30f,-1e30f,-1e30f,-1e30f};
  if (hm){
    #pragma unroll 2
    for (int t = 0; t < nv; t++){
      float4 tb = s_box[t];
      float ar3 = s_ar3[t];
      #pragma unroll
      for (int k = 0; k < 4; k++){
        float wi = fmaxf(fminf(c.phx[k], tb.z) - fmaxf(c.plx[k], tb.x), 0.f);
        float hi = fminf(c.phy[k], tb.w) - fmaxf(c.ply[k], tb.y);
        vmax[k] = fmaxf(vmax[k], fmaf(wi, hi, -ar3));     // iou>.5 <=> ai-at/3 > ap/3
      }
    }
  }
  #pragma unroll
  for (int k = 0; k < 4; k++){
    if (un[k] && !(vmax[k] > c.ap3[k])){ acc[2] += -clogf_(1.f - c.so[k]); acc[4] += c.so[k]*c.so[k]; }
  }
}

// scalar variant for L2 (FSQ=361, not divisible by 4)
struct Ctx2 {
  float so[4], plx[4], ply[4], phx[4], phy[4], ap3[4];
  int base;
};

__device__ __forceinline__ void main_pre2(const float* __restrict__ x, int b, int chunk, Ctx2& c){
  constexpr int FSQ = FSQ2;
  constexpr float invs = 0.03125f;
  c.base = chunk*CELLS + (int)threadIdx.x;
  #pragma unroll
  for (int k = 0; k < 4; k++){
    int cc = c.base + k*TPB;
    c.so[k] = 0.f; c.plx[k] = 3e4f; c.phx[k] = 3e4f; c.ply[k] = 0.f; c.phy[k] = 0.f; c.ap3[k] = 1.f;
    if (cc < 3*FSQ){
      int a = cc/FSQ, cell = cc - a*FSQ;
      const float* xp = x + (b*255 + a*85)*FSQ + cell;
      c.so[k] = sigf_(__ldg(xp + 4*FSQ));
      float AW = cANW[6+a]*invs, AH = cANH[6+a]*invs;
      float pw = __expf(__ldg(xp+2*FSQ))*AW, ph = __expf(__ldg(xp+3*FSQ))*AH;
      float px = (float)(cell % 19) + sigf_(__ldg(xp));
      float py = (float)(cell / 19) + sigf_(__ldg(xp+FSQ));
      float hw = 0.5f*pw, hh = 0.5f*ph;
      c.plx[k] = px-hw; c.phx[k] = px+hw; c.ply[k] = py-hh; c.phy[k] = py+hh;
      c.ap3[k] = pw*ph*(1.0f/3.0f);
    }
  }
}

__device__ __forceinline__ void main_post2(const Ctx2& c, int nv, int hm,
    const float4* s_box, const float* s_ar3, const unsigned char* s_mbit, float* acc){
  constexpr int FSQ = FSQ2;
  bool un[4] = {false,false,false,false};
  #pragma unroll
  for (int k = 0; k < 4; k++){
    int cc = c.base + k*TPB;
    if (cc < 3*FSQ){
      if (s_mbit[(int)threadIdx.x + k*TPB]){ acc[2] += -clogf_(c.so[k]); float e = c.so[k]-1.f; acc[4] += e*e; }
      else un[k] = true;
    }
  }
  float vmax[4] = {-1e30f,-1e30f,-1e30f,-1e30f};
  if (hm){
    for (int t = 0; t < nv; t++){
      float4 tb = s_box[t];
      float ar3 = s_ar3[t];
      #pragma unroll
      for (int k = 0; k < 4; k++){
        float wi = fmaxf(fminf(c.phx[k], tb.z) - fmaxf(c.plx[k], tb.x), 0.f);
        float hi = fminf(c.phy[k], tb.w) - fmaxf(c.ply[k], tb.y);
        vmax[k] = fmaxf(vmax[k], fmaf(wi, hi, -ar3));
      }
    }
  }
  #pragma unroll
  for (int k = 0; k < 4; k++){
    if (un[k] && !(vmax[k] > c.ap3[k])){ acc[2] += -clogf_(1.f - c.so[k]); acc[4] += c.so[k]*c.so[k]; }
  }
}

// ------------------------------------------------------------------ THE kernel: fully block-local, one launch
__global__ __launch_bounds__(TPB) void k_all(
    const float* __restrict__ x0, const float* __restrict__ x1, const float* __restrict__ x2,
    const float* __restrict__ labels, float* __restrict__ gout)
{
  __shared__ float4 s_box[NT];
  __shared__ float  s_ar3[NT];
  __shared__ __align__(4) unsigned char s_mbit[CELLS];
  __shared__ float  s_lab[NT][5];
  __shared__ int    s_key[NT];
  __shared__ int    s_win[NT];
  __shared__ float  s_red[5];
  __shared__ int    s_cnt;
  __shared__ int    s_last;

  int bid = blockIdx.x, tid = threadIdx.x;
  if (tid < 5) s_red[tid] = 0.f;
  float acc[5] = {0.f,0.f,0.f,0.f,0.f};

  if (bid < MATCHB){
    // ================= MATCH BLOCK (one per b): self-contained =================
    int b = bid;
    int key = -1;
    if (tid < NT){
      const float* lp = labels + (b*NT + tid)*5;
      float a0 = lp[0], a1 = lp[1], a2 = lp[2], a3 = lp[3], a4 = lp[4];
      s_lab[tid][0]=a0; s_lab[tid][1]=a1; s_lab[tid][2]=a2; s_lab[tid][3]=a3; s_lab[tid][4]=a4;
      bool valid = (a0+a1+a2+a3+a4) > 0.0f;
      if (valid){
        int bi = ciou_argmax((a2-a0)*0.125f, (a3-a1)*0.125f);
        int Lm = bi/3;
        const float invsA[3] = {0.125f, 0.0625f, 0.03125f};
        const int   fsA[3]   = {76, 38, 19};
        float invs = invsA[Lm]; int fs = fsA[Lm];
        float tx = (a2+a0)*(0.5f*invs), ty = (a3+a1)*(0.5f*invs);
        int ii = (int)tx; ii = ii < 0 ? 0 : (ii > fs-1 ? fs-1 : ii);
        int jj = (int)ty; jj = jj < 0 ? 0 : (jj > fs-1 ? fs-1 : jj);
        int cc = (bi - 3*Lm)*fs*fs + jj*fs + ii;      // < 17328 < 2^16
        key = (Lm << 16) | cc;
      }
      s_key[tid] = key;
    }
    __syncthreads();
    if (tid < NT){
      int w = 0;
      if (key >= 0){                                   // winner = last t with this (level,cell)
        w = 1;
        for (int t2 = tid+1; t2 < NT; t2++) if (s_key[t2] == key){ w = 0; break; }
      }
      s_win[tid] = w;
    }
    __syncthreads();
    int wrp = tid >> 5, lane = tid & 31;
    for (int t = wrp; t < NT; t += 8){                 // warp-uniform entry selection
      if (!s_win[t]) continue;
      int k2 = s_key[t];
      int Lm = k2 >> 16, cc = k2 & 0xFFFF;
      const int   fsqA[3]  = {FSQ0, FSQ1, FSQ2};
      const float invsA[3] = {0.125f, 0.0625f, 0.03125f};
      const float* x = (Lm==0) ? x0 : ((Lm==1) ? x1 : x2);
      int FSQ = fsqA[Lm];
      float invs = invsA[Lm];
      int a = cc/FSQ, cell = cc - a*FSQ;
      const float* xp = x + (b*255 + a*85)*FSQ + cell;
      float a0 = s_lab[t][0], a1 = s_lab[t][1], a2 = s_lab[t][2], a3 = s_lab[t][3], a4 = s_lab[t][4];
      float tx = (a2+a0)*(0.5f*invs), ty = (a3+a1)*(0.5f*invs);
      float tw = (a2-a0)*invs,        th = (a3-a1)*invs;
      float scl = sqrtf(2.0f - tw*th/(float)FSQ);
      int cl = (int)a4;
      for (int c = lane; c < NCLS; c += 32){
        float s = sigf_(__ldg(xp + (5+c)*FSQ));
        if (c == cl){ acc[3] += -clogf_(s);       float er = s-1.f; acc[4] += er*er; }
        else        { acc[3] += -clogf_(1.f - s); acc[4] += s*s; }
      }
      if (lane == 0){
        float AW = cANW[3*Lm+a]*invs, AH = cANH[3*Lm+a]*invs;
        float o0 = __ldg(xp), o1 = __ldg(xp+FSQ), o2 = __ldg(xp+2*FSQ), o3 = __ldg(xp+3*FSQ);
        float s0 = sigf_(o0), s1 = sigf_(o1);
        float fx = tx - truncf(tx), fy = ty - truncf(ty);
        float lw = __logf(tw/AW + 1e-16f), lh = __logf(th/AH + 1e-16f);
        float w2 = scl*scl;
        acc[0] += w2*( -(fx*clogf_(s0) + (1.f-fx)*clogf_(1.f-s0))
                       -(fy*clogf_(s1) + (1.f-fy)*clogf_(1.f-s1)) );
        float dx = (o2-lw)*scl, dy = (o3-lh)*scl;
        acc[1] += 0.5f*(dx*dx + dy*dy);
        float e0 = s0-fx, e1 = s1-fy;
        acc[4] += e0*e0 + e1*e1 + dx*dx + dy*dy;
      }
    }
  } else {
    // ================= MAIN BLOCK: self-contained prep + obj loss =================
    int mbid = bid - MATCHB;
    int Lv, b, chunk;
    if (mbid < NB*CH0)            { Lv = 0; b = mbid/CH0;                    chunk = mbid - b*CH0; }
    else if (mbid < NB*(CH0+CH1)) { int r = mbid - NB*CH0;       Lv = 1; b = r/CH1; chunk = r - b*CH1; }
    else                          { int r = mbid - NB*(CH0+CH1); Lv = 2; b = r/CH2; chunk = r - b*CH2; }

    // phase A: in-block truth prep (bitmap zero + boxes + argmax)
    ((int*)s_mbit)[tid] = 0;                           // 256 ints = 1024 B
    if (tid == 0) s_cnt = 0;
    int mi = -1;
    if (tid < NT){
      const float* lp = labels + (b*NT + tid)*5;
      float a0 = lp[0], a1 = lp[1], a2 = lp[2], a3 = lp[3], a4 = lp[4];
      bool valid = (a0+a1+a2+a3+a4) > 0.0f;
      if (valid){
        int bi = ciou_argmax((a2-a0)*0.125f, (a3-a1)*0.125f);
        float invs = (Lv==0) ? 0.125f : ((Lv==1) ? 0.0625f : 0.03125f);
        int   fs   = (Lv==0) ? 76 : ((Lv==1) ? 38 : 19);
        float tx = (a2+a0)*(0.5f*invs), ty = (a3+a1)*(0.5f*invs);
        float tw = (a2-a0)*invs,        th = (a3-a1)*invs;
        int p = atomicAdd(&s_cnt, 1);                  // order-free: feeds exact max only
        s_box[p] = make_float4(tx - tw*0.5f, ty - th*0.5f, tx + tw*0.5f, ty + th*0.5f);
        s_ar3[p] = tw*th*(1.0f/3.0f);
        if (bi/3 == Lv){
          int ii = (int)tx; ii = ii < 0 ? 0 : (ii > fs-1 ? fs-1 : ii);
          int jj = (int)ty; jj = jj < 0 ? 0 : (jj > fs-1 ? fs-1 : jj);
          mi = (bi - 3*Lv)*fs*fs + jj*fs + ii;
        }
      }
    }
    int hm = __syncthreads_or(mi >= 0);                // also fences s_box/s_cnt/bitmap-zero
    if (mi >= 0){
      int off = mi - chunk*CELLS;
      if (off >= 0 && off < CELLS) s_mbit[off] = 1;    // boolean is sufficient for obj path
    }
    int nv = s_cnt;

    // phase B: channel loads + pred boxes, sync (covers bitmap), ignore loop
    if (Lv == 0){
      Ctx<0,76> c; main_pre<0,76>(x0, b, chunk, c);
      __syncthreads();
      main_post<0,76>(c, nv, hm, s_box, s_ar3, s_mbit, acc);
    } else if (Lv == 1){
      Ctx<1,38> c; main_pre<1,38>(x1, b, chunk, c);
      __syncthreads();
      main_post<1,38>(c, nv, hm, s_box, s_ar3, s_mbit, acc);
    } else {
      Ctx2 c; main_pre2(x2, b, chunk, c);
      __syncthreads();
      main_post2(c, nv, hm, s_box, s_ar3, s_mbit, acc);
    }
  }

  // ================= block reduction -> per-block partial =================
  #pragma unroll
  for (int k = 0; k < 5; k++){
    float v = acc[k];
    #pragma unroll
    for (int off = 16; off > 0; off >>= 1) v += __shfl_down_sync(0xffffffffu, v, off);
    if ((tid & 31) == 0 && v != 0.f) atomicAdd(&s_red[k], v);
  }
  __syncthreads();
  if (tid < 5){ g_partial[bid][tid] = s_red[tid]; __threadfence(); }
  __syncthreads();
  if (tid == 0) s_last = (atomicAdd(&g_done, 1) == GRID-1);
  __syncthreads();

  // ================= last block: final sum, writes all of gout =================
  if (s_last){
    int wrp = tid >> 5, lane = tid & 31;
    if (wrp < 5){
      float v = 0.f;
      for (int r = lane; r < GRID; r += 32) v += __ldcg(&g_partial[r][wrp]);
      #pragma unroll
      for (int off = 16; off > 0; off >>= 1) v += __shfl_down_sync(0xffffffffu, v, off);
      if (lane == 0) s_red[wrp] = v;
    }
    __syncthreads();
    if (tid == 0){
      g_done = 0;                                      // restore invariant for next replay
      float lxy = s_red[0], lwh = s_red[1], lobj = s_red[2], lcls = s_red[3], ll2 = s_red[4];
      gout[0] = lxy + lwh + lobj + lcls;
      gout[1] = lxy; gout[2] = lwh; gout[3] = lobj; gout[4] = lcls; gout[5] = ll2;
    }
  }
}

// ------------------------------------------------------------------ launch: ONE node
extern "C" void kernel_launch(void* const* d_in, const int* in_sizes, int n_in,
                              void* d_out, int out_size)
{
  const float* x0     = (const float*)d_in[0];
  const float* x1     = (const float*)d_in[1];
  const float* x2     = (const float*)d_in[2];
  const float* labels = (const float*)d_in[3];
  float* gout = (float*)d_out;
  (void)in_sizes; (void)n_in; (void)out_size;

  k_all<<<GRID, TPB>>>(x0, x1, x2, labels, gout);
}